// round 3
// baseline (speedup 1.0000x reference)
#include <cuda_runtime.h>
#include <cuda_fp16.h>
#include <math_constants.h>

#define VOCAB    100000
#define RAND_DIM 100
#define WAE      50
#define CLS      4
#define VDIM     100
#define NPATH    16384
#define PLEN     50
#define HDIM     150     // RAND_DIM + WAE
#define PADT     160     // fused table row pitch in halves: 320 B = 10 sectors
#define RPB      128     // vocab rows per prep block
#define SE_PITCH 132     // sE pitch (floats): 16B-aligned ull2 reads, 4-way fill conflict

typedef unsigned long long ull;

// Fused gather table: row v = [fp16 E_td[v][0:100] | fp16 (E_wae@W_enc)[v][0:50] | pad]
__device__ __half g_T[(size_t)VOCAB * PADT];   // 32 MB
// Global max-pool accumulator [HDIM]
__device__ float g_max[HDIM];

// ---------------------------------------------------------------------------
// packed f32x2 helpers
// ---------------------------------------------------------------------------
__device__ __forceinline__ ull fma2(ull a, ull b, ull c) {
    ull d;
    asm("fma.rn.f32x2 %0, %1, %2, %3;" : "=l"(d) : "l"(a), "l"(b), "l"(c));
    return d;
}
__device__ __forceinline__ ull dup2(float v) {
    ull d;
    asm("mov.b64 %0, {%1, %1};" : "=l"(d) : "f"(v));
    return d;
}
__device__ __forceinline__ void unpack2(ull v, float& lo, float& hi) {
    asm("mov.b64 {%0, %1}, %2;" : "=f"(lo), "=f"(hi) : "l"(v));
}
__device__ __forceinline__ __half2 asH2(unsigned u) {
    return *reinterpret_cast<__half2*>(&u);
}
__device__ __forceinline__ void atomicMaxF(float* addr, float v) {
    if (v >= 0.f) atomicMax((int*)addr, __float_as_int(v));
    else          atomicMin((unsigned int*)addr, __float_as_uint(v));
}

// ---------------------------------------------------------------------------
// Kernel 1 (prep): per block of 128 vocab rows:
//   (a) convert E_td rows -> g_T[:, 0:100] (fp16)
//   (b) G = E_wae @ W_enc -> g_T[:, 100:150] (fp16)
// GEMM: 16 rows/warp as 8 row-pairs; fma.rn.f32x2 does (row_even,row_odd) per
// output col. E staged transposed+rowpair-packed in smem so 4 broadcast
// LDS.128 feed all 16 FFMA2 of a k-step.  Block 0 also inits g_max.
// ---------------------------------------------------------------------------
__global__ void __launch_bounds__(256, 3)
prep_kernel(const float* __restrict__ E_wae,
            const float* __restrict__ W_enc,
            const float* __restrict__ E_td) {
    extern __shared__ float sh[];
    float* sE = sh;                      // [VDIM][SE_PITCH]  52.8 KB
    float* sW = sh + VDIM * SE_PITCH;    // [VDIM][WAE]       20 KB

    int tid  = threadIdx.x;
    int row0 = blockIdx.x * RPB;
    if (blockIdx.x == 0 && tid < HDIM) g_max[tid] = -CUDART_INF_F;

    for (int i = tid; i < VDIM * WAE; i += 256) sW[i] = W_enc[i];

    // stage E_wae transposed: sE[k*SE_PITCH + r] = E_wae[row0+r][k]
    for (int i = tid; i < RPB * VDIM; i += 256) {
        int r = i / VDIM, k = i % VDIM;
        int row = row0 + r;
        sE[k * SE_PITCH + r] = (row < VOCAB) ? E_wae[(size_t)row * VDIM + k] : 0.f;
    }

    // convert E_td rows -> fp16 table (independent of the GEMM; overlaps)
    {
        const float4* E4 = (const float4*)E_td;   // 25 float4 per row
        for (int i = tid; i < RPB * 25; i += 256) {
            int r = i / 25, c = i % 25;
            int row = row0 + r;
            if (row < VOCAB) {
                float4 v = __ldg(&E4[(size_t)row * 25 + c]);
                __half2* dst = (__half2*)(g_T + (size_t)row * PADT + 4 * c);
                dst[0] = __floats2half2_rn(v.x, v.y);
                dst[1] = __floats2half2_rn(v.z, v.w);
            }
        }
    }
    __syncthreads();

    int w = tid >> 5, lane = tid & 31;
    bool hiCol = lane < (WAE - 32);      // lanes 0..17 own cols 32..49

    ull acc[8][2];
    #pragma unroll
    for (int q = 0; q < 8; q++) { acc[q][0] = 0ull; acc[q][1] = 0ull; }

    #pragma unroll 2
    for (int k = 0; k < VDIM; k++) {
        const ull* ep = (const ull*)(sE + k * SE_PITCH + 16 * w);  // 8 row-pairs, broadcast
        float w0 = sW[k * WAE + lane];
        float w1 = hiCol ? sW[k * WAE + 32 + lane] : 0.f;
        ull wd0 = dup2(w0), wd1 = dup2(w1);
        #pragma unroll
        for (int q = 0; q < 8; q++) {
            ull e = ep[q];
            acc[q][0] = fma2(e, wd0, acc[q][0]);
            acc[q][1] = fma2(e, wd1, acc[q][1]);
        }
    }

    int rbase = row0 + 16 * w;
    #pragma unroll
    for (int q = 0; q < 8; q++) {
        int r0 = rbase + 2 * q;
        float lo, hi;
        unpack2(acc[q][0], lo, hi);
        if (r0     < VOCAB) g_T[(size_t)r0       * PADT + RAND_DIM + lane] = __float2half(lo);
        if (r0 + 1 < VOCAB) g_T[(size_t)(r0 + 1) * PADT + RAND_DIM + lane] = __float2half(hi);
        if (hiCol) {
            unpack2(acc[q][1], lo, hi);
            if (r0     < VOCAB) g_T[(size_t)r0       * PADT + RAND_DIM + 32 + lane] = __float2half(lo);
            if (r0 + 1 < VOCAB) g_T[(size_t)(r0 + 1) * PADT + RAND_DIM + 32 + lane] = __float2half(hi);
        }
    }
}

// ---------------------------------------------------------------------------
// Kernel 2: gather. One warp per path; lanes 0..18 each own one 16B chunk
// (8 halves = dims 8l..8l+7) of the fused row -> ONE LDG.128 per token.
// Token pairs summed in fp16 (HADD2) then converted & accumulated in fp32.
// ---------------------------------------------------------------------------
__global__ void __launch_bounds__(256)
path_gather_kernel(const int* __restrict__ x,
                   const float* __restrict__ b_enc) {
    __shared__ float smax[HDIM];
    int tid = threadIdx.x;
    for (int i = tid; i < HDIM; i += 256) smax[i] = -CUDART_INF_F;
    __syncthreads();

    int w = tid >> 5, lane = tid & 31;
    int p = blockIdx.x * 8 + w;
    const int* xp = x + (size_t)p * PLEN;

    int tA = xp[lane];
    int tB = (lane < PLEN - 32) ? xp[32 + lane] : 0;

    bool act = lane < 19;                    // chunks covering dims 0..151
    const uint4* T4 = (const uint4*)g_T;     // 20 uint4 per row

    float2 a0 = {0.f, 0.f}, a1 = {0.f, 0.f}, a2 = {0.f, 0.f}, a3 = {0.f, 0.f};

    #pragma unroll 5
    for (int t = 0; t < PLEN; t += 2) {
        int tok0 = (t < 32)     ? __shfl_sync(0xffffffffu, tA, t)
                                : __shfl_sync(0xffffffffu, tB, t - 32);
        int tok1 = (t + 1 < 32) ? __shfl_sync(0xffffffffu, tA, t + 1)
                                : __shfl_sync(0xffffffffu, tB, t - 31);
        if (act) {
            uint4 va = __ldg(&T4[(size_t)tok0 * 20 + lane]);
            uint4 vb = __ldg(&T4[(size_t)tok1 * 20 + lane]);
            __half2 s0 = __hadd2(asH2(va.x), asH2(vb.x));
            __half2 s1 = __hadd2(asH2(va.y), asH2(vb.y));
            __half2 s2 = __hadd2(asH2(va.z), asH2(vb.z));
            __half2 s3 = __hadd2(asH2(va.w), asH2(vb.w));
            float2 f;
            f = __half22float2(s0); a0.x += f.x; a0.y += f.y;
            f = __half22float2(s1); a1.x += f.x; a1.y += f.y;
            f = __half22float2(s2); a2.x += f.x; a2.y += f.y;
            f = __half22float2(s3); a3.x += f.x; a3.y += f.y;
        }
    }

    if (act) {
        float f[8] = {a0.x, a0.y, a1.x, a1.y, a2.x, a2.y, a3.x, a3.y};
        int d0 = lane * 8;
        #pragma unroll
        for (int j = 0; j < 8; j++) {
            int d = d0 + j;
            if (d < RAND_DIM) {
                float v = f[j];
                v = (v > 0.f) ? v : 0.01f * v;                 // leaky_relu
                atomicMaxF(&smax[d], v);
            } else if (d < HDIM) {
                float v = fmaxf(f[j] + __ldg(&b_enc[d - RAND_DIM]), 0.f);  // relu
                atomicMaxF(&smax[d], v);
            }
        }
    }
    __syncthreads();

    for (int i = tid; i < HDIM; i += 256) atomicMaxF(&g_max[i], smax[i]);
}

// ---------------------------------------------------------------------------
// Kernel 3: logits -> softmax -> prob; loss = -log_softmax(prob)[argmax(y)]
// ---------------------------------------------------------------------------
__global__ void finalize_kernel(const float* __restrict__ w_out,
                                const float* __restrict__ b_out,
                                const int*   __restrict__ y,
                                float* __restrict__ out, int out_size) {
    int lane = threadIdx.x;
    float part[CLS] = {0.f, 0.f, 0.f, 0.f};
    for (int d = lane; d < HDIM; d += 32) {
        float m = g_max[d];
        #pragma unroll
        for (int c = 0; c < CLS; c++)
            part[c] = fmaf(w_out[c * HDIM + d], m, part[c]);
    }
    #pragma unroll
    for (int off = 16; off > 0; off >>= 1) {
        #pragma unroll
        for (int c = 0; c < CLS; c++)
            part[c] += __shfl_down_sync(0xffffffffu, part[c], off);
    }
    if (lane == 0) {
        float logits[CLS], prob[CLS];
        float mx = -CUDART_INF_F;
        #pragma unroll
        for (int c = 0; c < CLS; c++) {
            logits[c] = part[c] + b_out[c];
            mx = fmaxf(mx, logits[c]);
        }
        float s = 0.f;
        #pragma unroll
        for (int c = 0; c < CLS; c++) { prob[c] = expf(logits[c] - mx); s += prob[c]; }
        #pragma unroll
        for (int c = 0; c < CLS; c++) prob[c] /= s;

        int label = 0, best = y[0];
        #pragma unroll
        for (int c = 1; c < CLS; c++) if (y[c] > best) { best = y[c]; label = c; }

        float mx2 = prob[0];
        #pragma unroll
        for (int c = 1; c < CLS; c++) mx2 = fmaxf(mx2, prob[c]);
        float s2 = 0.f;
        #pragma unroll
        for (int c = 0; c < CLS; c++) s2 += expf(prob[c] - mx2);
        float loss = -(prob[label] - (mx2 + logf(s2)));

        for (int c = 0; c < CLS && c < out_size; c++) out[c] = prob[c];
        if (out_size > CLS) out[CLS] = loss;
    }
}

// ---------------------------------------------------------------------------
extern "C" void kernel_launch(void* const* d_in, const int* in_sizes, int n_in,
                              void* d_out, int out_size) {
    const int*   x     = (const int*)  d_in[0];
    const int*   y     = (const int*)  d_in[1];
    const float* E_td  = (const float*)d_in[2];
    const float* E_wae = (const float*)d_in[3];
    const float* W_enc = (const float*)d_in[4];
    const float* b_enc = (const float*)d_in[5];
    const float* w_out = (const float*)d_in[6];
    const float* b_out = (const float*)d_in[7];
    float* out = (float*)d_out;

    const int smem_prep = (VDIM * SE_PITCH + VDIM * WAE) * sizeof(float);  // 72.8 KB
    cudaFuncSetAttribute(prep_kernel,
                         cudaFuncAttributeMaxDynamicSharedMemorySize, smem_prep);

    prep_kernel<<<(VOCAB + RPB - 1) / RPB, 256, smem_prep>>>(E_wae, W_enc, E_td);
    path_gather_kernel<<<NPATH / 8, 256>>>(x, b_enc);
    finalize_kernel<<<1, 32>>>(w_out, b_out, y, out, out_size);
}

// round 4
// speedup vs baseline: 1.6462x; 1.6462x over previous
#include <cuda_runtime.h>
#include <cuda_fp16.h>
#include <math_constants.h>

#define VOCAB    100000
#define RAND_DIM 100
#define WAE      50
#define CLS      4
#define VDIM     100
#define NPATH    16384
#define PLEN     50
#define HDIM     150     // RAND_DIM + WAE
#define PADT     200     // fused table row pitch in halves: 400 B = exactly 25 uint4

typedef unsigned long long ull;

// Fused gather table: row v = [fp16 E_td[v][0:100] | fp16 E_wae[v][0:100]]  (40 MB)
__device__ __half g_T[(size_t)VOCAB * PADT];
// Global max-pool accumulator [HDIM]
__device__ float g_max[HDIM];

// ---------------------------------------------------------------------------
__device__ __forceinline__ ull fma2(ull a, ull b, ull c) {
    ull d;
    asm("fma.rn.f32x2 %0, %1, %2, %3;" : "=l"(d) : "l"(a), "l"(b), "l"(c));
    return d;
}
__device__ __forceinline__ ull dup2(float v) {
    ull d;
    asm("mov.b64 %0, {%1, %1};" : "=l"(d) : "f"(v));
    return d;
}
__device__ __forceinline__ void unpack2(ull v, float& lo, float& hi) {
    asm("mov.b64 {%0, %1}, %2;" : "=f"(lo), "=f"(hi) : "l"(v));
}
__device__ __forceinline__ __half2 asH2(unsigned u) {
    return *reinterpret_cast<__half2*>(&u);
}
__device__ __forceinline__ void atomicMaxF(float* addr, float v) {
    if (v >= 0.f) atomicMax((int*)addr, __float_as_int(v));
    else          atomicMin((unsigned int*)addr, __float_as_uint(v));
}
__device__ __forceinline__ ull packh(float a, float b, float c, float d) {
    __half2 h0 = __floats2half2_rn(a, b);
    __half2 h1 = __floats2half2_rn(c, d);
    unsigned lo = *reinterpret_cast<unsigned*>(&h0);
    unsigned hi = *reinterpret_cast<unsigned*>(&h1);
    return (ull)lo | ((ull)hi << 32);
}

// ---------------------------------------------------------------------------
// Kernel 1: pure streaming fp32 -> fp16 table build. Zero FLOP GEMM work —
// the WAE linear moved into the gather kernel (6x less math per-path).
// One float4 read -> one 8B packed write per iteration, both coalesced.
// ---------------------------------------------------------------------------
__global__ void __launch_bounds__(256)
convert_kernel(const float* __restrict__ E_td,
               const float* __restrict__ E_wae) {
    if (blockIdx.x == 0 && threadIdx.x < HDIM) g_max[threadIdx.x] = -CUDART_INF_F;

    const float4* A = (const float4*)E_td;    // 25 float4 per row
    const float4* B = (const float4*)E_wae;   // 25 float4 per row
    ull* T = (ull*)g_T;                       // 50 ull per row

    const size_t N = (size_t)VOCAB * 25;
    size_t stride = (size_t)gridDim.x * blockDim.x;
    size_t i0 = (size_t)blockIdx.x * blockDim.x + threadIdx.x;

    for (size_t i = i0; i < N; i += stride) {
        size_t row = i / 25, j = i % 25;
        float4 v = __ldg(&A[i]);
        T[row * 50 + j] = packh(v.x, v.y, v.z, v.w);
    }
    for (size_t i = i0; i < N; i += stride) {
        size_t row = i / 25, j = i % 25;
        float4 v = __ldg(&B[i]);
        T[row * 50 + 25 + j] = packh(v.x, v.y, v.z, v.w);
    }
}

// ---------------------------------------------------------------------------
// Kernel 2: gather + per-path WAE linear + activations + max-pool.
// One warp per path; lanes 0..24 each own one 16B chunk (dims 8l..8l+7) of
// the fused row -> ONE LDG.128 per token per warp. Token pairs summed with
// HADD2 then accumulated fp32. Dims 0..99 -> leaky_relu + max. Dims
// 100..199 = bow -> per-warp smem -> 100x50 linear (f32x2 col-pairs, W_enc
// reinterpreted as ull[100][25] in smem) -> +b_enc, relu, max.
// ---------------------------------------------------------------------------
__global__ void __launch_bounds__(256)
path_gather_kernel(const int* __restrict__ x,
                   const float* __restrict__ W_enc,
                   const float* __restrict__ b_enc) {
    __shared__ float smax[HDIM];
    __shared__ ull   sW2[VDIM * 25];     // [k][col-pair l] : W_enc cols (2l,2l+1)  20 KB
    __shared__ float sbow[8][VDIM];      // per-warp bag-of-words                  3.2 KB

    int tid = threadIdx.x;
    for (int i = tid; i < HDIM; i += 256) smax[i] = -CUDART_INF_F;
    {   // W_enc is row-major [100][50]; adjacent col pair = one ull, direct copy
        const ull* Ws = (const ull*)W_enc;
        for (int i = tid; i < VDIM * 25; i += 256) sW2[i] = Ws[i];
    }
    __syncthreads();

    int w = tid >> 5, lane = tid & 31;
    int p = blockIdx.x * 8 + w;
    const int* xp = x + (size_t)p * PLEN;

    int tA = xp[lane];
    int tB = (lane < PLEN - 32) ? xp[32 + lane] : 0;

    bool act = lane < 25;
    const uint4* T4 = (const uint4*)g_T;     // 25 uint4 per row

    float2 a0 = {0.f, 0.f}, a1 = {0.f, 0.f}, a2 = {0.f, 0.f}, a3 = {0.f, 0.f};

    #pragma unroll 5
    for (int t = 0; t < PLEN; t += 2) {
        int tok0 = (t < 32)     ? __shfl_sync(0xffffffffu, tA, t)
                                : __shfl_sync(0xffffffffu, tB, t - 32);
        int tok1 = (t + 1 < 32) ? __shfl_sync(0xffffffffu, tA, t + 1)
                                : __shfl_sync(0xffffffffu, tB, t - 31);
        if (act) {
            uint4 va = __ldg(&T4[(size_t)tok0 * 25 + lane]);
            uint4 vb = __ldg(&T4[(size_t)tok1 * 25 + lane]);
            __half2 s0 = __hadd2(asH2(va.x), asH2(vb.x));
            __half2 s1 = __hadd2(asH2(va.y), asH2(vb.y));
            __half2 s2 = __hadd2(asH2(va.z), asH2(vb.z));
            __half2 s3 = __hadd2(asH2(va.w), asH2(vb.w));
            float2 f;
            f = __half22float2(s0); a0.x += f.x; a0.y += f.y;
            f = __half22float2(s1); a1.x += f.x; a1.y += f.y;
            f = __half22float2(s2); a2.x += f.x; a2.y += f.y;
            f = __half22float2(s3); a3.x += f.x; a3.y += f.y;
        }
    }

    if (act) {
        float f[8] = {a0.x, a0.y, a1.x, a1.y, a2.x, a2.y, a3.x, a3.y};
        int d0 = lane * 8;
        #pragma unroll
        for (int j = 0; j < 8; j++) {
            int d = d0 + j;
            if (d < RAND_DIM) {                     // path_random dim: leaky_relu
                float v = f[j];
                v = (v > 0.f) ? v : 0.01f * v;
                atomicMaxF(&smax[d], v);
            } else {                                // bow dim: stage for the linear
                sbow[w][d - RAND_DIM] = f[j];
            }
        }
    }
    __syncwarp();

    // per-path linear: out[2l,2l+1] = sum_k bow[k] * W[k][2l,2l+1]
    if (act) {
        ull accA = 0ull, accB = 0ull;
        const float* bw = sbow[w];
        #pragma unroll 10
        for (int k = 0; k < VDIM; k += 2) {
            accA = fma2(dup2(bw[k]),     sW2[k * 25 + lane],       accA);
            accB = fma2(dup2(bw[k + 1]), sW2[(k + 1) * 25 + lane], accB);
        }
        float c0, c1, e0, e1;
        unpack2(accA, c0, c1);
        unpack2(accB, e0, e1);
        c0 += e0; c1 += e1;
        int c = 2 * lane;
        float v0 = fmaxf(c0 + __ldg(&b_enc[c]),     0.f);   // relu; leaky id on >=0
        float v1 = fmaxf(c1 + __ldg(&b_enc[c + 1]), 0.f);
        atomicMaxF(&smax[RAND_DIM + c],     v0);
        atomicMaxF(&smax[RAND_DIM + c + 1], v1);
    }
    __syncthreads();

    for (int i = tid; i < HDIM; i += 256) atomicMaxF(&g_max[i], smax[i]);
}

// ---------------------------------------------------------------------------
// Kernel 3: logits -> softmax -> prob; loss = -log_softmax(prob)[argmax(y)]
// ---------------------------------------------------------------------------
__global__ void finalize_kernel(const float* __restrict__ w_out,
                                const float* __restrict__ b_out,
                                const int*   __restrict__ y,
                                float* __restrict__ out, int out_size) {
    int lane = threadIdx.x;
    float part[CLS] = {0.f, 0.f, 0.f, 0.f};
    for (int d = lane; d < HDIM; d += 32) {
        float m = g_max[d];
        #pragma unroll
        for (int c = 0; c < CLS; c++)
            part[c] = fmaf(w_out[c * HDIM + d], m, part[c]);
    }
    #pragma unroll
    for (int off = 16; off > 0; off >>= 1) {
        #pragma unroll
        for (int c = 0; c < CLS; c++)
            part[c] += __shfl_down_sync(0xffffffffu, part[c], off);
    }
    if (lane == 0) {
        float logits[CLS], prob[CLS];
        float mx = -CUDART_INF_F;
        #pragma unroll
        for (int c = 0; c < CLS; c++) {
            logits[c] = part[c] + b_out[c];
            mx = fmaxf(mx, logits[c]);
        }
        float s = 0.f;
        #pragma unroll
        for (int c = 0; c < CLS; c++) { prob[c] = expf(logits[c] - mx); s += prob[c]; }
        #pragma unroll
        for (int c = 0; c < CLS; c++) prob[c] /= s;

        int label = 0, best = y[0];
        #pragma unroll
        for (int c = 1; c < CLS; c++) if (y[c] > best) { best = y[c]; label = c; }

        float mx2 = prob[0];
        #pragma unroll
        for (int c = 1; c < CLS; c++) mx2 = fmaxf(mx2, prob[c]);
        float s2 = 0.f;
        #pragma unroll
        for (int c = 0; c < CLS; c++) s2 += expf(prob[c] - mx2);
        float loss = -(prob[label] - (mx2 + logf(s2)));

        for (int c = 0; c < CLS && c < out_size; c++) out[c] = prob[c];
        if (out_size > CLS) out[CLS] = loss;
    }
}

// ---------------------------------------------------------------------------
extern "C" void kernel_launch(void* const* d_in, const int* in_sizes, int n_in,
                              void* d_out, int out_size) {
    const int*   x     = (const int*)  d_in[0];
    const int*   y     = (const int*)  d_in[1];
    const float* E_td  = (const float*)d_in[2];
    const float* E_wae = (const float*)d_in[3];
    const float* W_enc = (const float*)d_in[4];
    const float* b_enc = (const float*)d_in[5];
    const float* w_out = (const float*)d_in[6];
    const float* b_out = (const float*)d_in[7];
    float* out = (float*)d_out;

    convert_kernel<<<1184, 256>>>(E_td, E_wae);          // 8 blocks/SM x 148
    path_gather_kernel<<<NPATH / 8, 256>>>(x, W_enc, b_enc);
    finalize_kernel<<<1, 32>>>(w_out, b_out, y, out, out_size);
}

// round 5
// speedup vs baseline: 1.7303x; 1.0511x over previous
#include <cuda_runtime.h>
#include <cuda_fp16.h>
#include <math_constants.h>

#define VOCAB    100000
#define RAND_DIM 100
#define WAE      50
#define CLS      4
#define VDIM     100
#define NPATH    16384
#define PLEN     50
#define HDIM     150     // RAND_DIM + WAE
#define PADT     208     // table row pitch in halves: 416 B = 13 aligned sectors, 26 uint4
#define NBLK     (NPATH / 8)

typedef unsigned long long ull;

// Fused gather table: row v = [fp16 E_td[v][0:100] | fp16 E_wae[v][0:100] | pad]
__device__ __half g_T[(size_t)VOCAB * PADT];   // ~41.6 MB
__device__ float  g_max[HDIM];
__device__ int    g_done;

// ---------------------------------------------------------------------------
__device__ __forceinline__ ull fma2(ull a, ull b, ull c) {
    ull d;
    asm("fma.rn.f32x2 %0, %1, %2, %3;" : "=l"(d) : "l"(a), "l"(b), "l"(c));
    return d;
}
__device__ __forceinline__ ull dup2(float v) {
    ull d;
    asm("mov.b64 %0, {%1, %1};" : "=l"(d) : "f"(v));
    return d;
}
__device__ __forceinline__ void unpack2(ull v, float& lo, float& hi) {
    asm("mov.b64 {%0, %1}, %2;" : "=f"(lo), "=f"(hi) : "l"(v));
}
__device__ __forceinline__ __half2 asH2(unsigned u) {
    return *reinterpret_cast<__half2*>(&u);
}
__device__ __forceinline__ void atomicMaxF(float* addr, float v) {
    if (v >= 0.f) atomicMax((int*)addr, __float_as_int(v));
    else          atomicMin((unsigned int*)addr, __float_as_uint(v));
}
__device__ __forceinline__ ull packh(float a, float b, float c, float d) {
    __half2 h0 = __floats2half2_rn(a, b);
    __half2 h1 = __floats2half2_rn(c, d);
    unsigned lo = *reinterpret_cast<unsigned*>(&h0);
    unsigned hi = *reinterpret_cast<unsigned*>(&h1);
    return (ull)lo | ((ull)hi << 32);
}

// ---------------------------------------------------------------------------
// Kernel 1: streaming fp32 -> fp16 table build. __ldcs on reads (stream data,
// never reused) so the table writes stay resident in L2 for the gather.
// ---------------------------------------------------------------------------
__global__ void __launch_bounds__(256)
convert_kernel(const float* __restrict__ E_td,
               const float* __restrict__ E_wae) {
    if (blockIdx.x == 0) {
        if (threadIdx.x < HDIM) g_max[threadIdx.x] = -CUDART_INF_F;
        if (threadIdx.x == 0)   g_done = 0;
    }

    const float4* A = (const float4*)E_td;    // 25 float4 per row
    const float4* B = (const float4*)E_wae;   // 25 float4 per row
    ull* T = (ull*)g_T;                       // 52 ull per row (50 data + 2 pad)

    const size_t N = (size_t)VOCAB * 25;
    size_t stride = (size_t)gridDim.x * blockDim.x;
    size_t i0 = (size_t)blockIdx.x * blockDim.x + threadIdx.x;

    for (size_t i = i0; i < N; i += stride) {
        size_t row = i / 25, j = i % 25;
        float4 v = __ldcs(&A[i]);
        T[row * 52 + j] = packh(v.x, v.y, v.z, v.w);
    }
    for (size_t i = i0; i < N; i += stride) {
        size_t row = i / 25, j = i % 25;
        float4 v = __ldcs(&B[i]);
        T[row * 52 + 25 + j] = packh(v.x, v.y, v.z, v.w);
    }
}

// ---------------------------------------------------------------------------
// Kernel 2: gather + per-path WAE linear + activations + max-pool + fused
// finalize (last block computes softmax/loss).
// One warp per path; lanes 0..24 own one 16B chunk (dims 8l..8l+7).
// 4 tokens per body -> 4 independent LDG.128 in flight, fp16 tree-add, one
// f32 convert+add per 4 tokens.
// ---------------------------------------------------------------------------
__global__ void __launch_bounds__(256)
path_gather_kernel(const int*   __restrict__ x,
                   const float* __restrict__ W_enc,
                   const float* __restrict__ b_enc,
                   const float* __restrict__ w_out,
                   const float* __restrict__ b_out,
                   const int*   __restrict__ y,
                   float* __restrict__ out, int out_size) {
    __shared__ float smax[HDIM];
    __shared__ ull   sW2[VDIM * 25];     // W_enc col-pairs                 20 KB
    __shared__ float sbow[8][VDIM];      // per-warp bag-of-words           3.2 KB
    __shared__ int   s_last;

    int tid = threadIdx.x;
    for (int i = tid; i < HDIM; i += 256) smax[i] = -CUDART_INF_F;
    {
        const ull* Ws = (const ull*)W_enc;
        for (int i = tid; i < VDIM * 25; i += 256) sW2[i] = Ws[i];
    }
    __syncthreads();

    int w = tid >> 5, lane = tid & 31;
    int p = blockIdx.x * 8 + w;
    const int* xp = x + (size_t)p * PLEN;

    int tA = xp[lane];
    int tB = (lane < PLEN - 32) ? xp[32 + lane] : 0;

    bool act = lane < 25;
    const uint4* T4 = (const uint4*)g_T;     // 26 uint4 per row

    float2 a0 = {0.f, 0.f}, a1 = {0.f, 0.f}, a2 = {0.f, 0.f}, a3 = {0.f, 0.f};

    #pragma unroll
    for (int t = 0; t < 48; t += 4) {
        int k0 = (t     < 32) ? __shfl_sync(0xffffffffu, tA, t)     : __shfl_sync(0xffffffffu, tB, t - 32);
        int k1 = (t + 1 < 32) ? __shfl_sync(0xffffffffu, tA, t + 1) : __shfl_sync(0xffffffffu, tB, t - 31);
        int k2 = (t + 2 < 32) ? __shfl_sync(0xffffffffu, tA, t + 2) : __shfl_sync(0xffffffffu, tB, t - 30);
        int k3 = (t + 3 < 32) ? __shfl_sync(0xffffffffu, tA, t + 3) : __shfl_sync(0xffffffffu, tB, t - 29);
        if (act) {
            uint4 v0 = __ldg(&T4[(size_t)k0 * 26 + lane]);
            uint4 v1 = __ldg(&T4[(size_t)k1 * 26 + lane]);
            uint4 v2 = __ldg(&T4[(size_t)k2 * 26 + lane]);
            uint4 v3 = __ldg(&T4[(size_t)k3 * 26 + lane]);
            __half2 s0 = __hadd2(__hadd2(asH2(v0.x), asH2(v1.x)), __hadd2(asH2(v2.x), asH2(v3.x)));
            __half2 s1 = __hadd2(__hadd2(asH2(v0.y), asH2(v1.y)), __hadd2(asH2(v2.y), asH2(v3.y)));
            __half2 s2 = __hadd2(__hadd2(asH2(v0.z), asH2(v1.z)), __hadd2(asH2(v2.z), asH2(v3.z)));
            __half2 s3 = __hadd2(__hadd2(asH2(v0.w), asH2(v1.w)), __hadd2(asH2(v2.w), asH2(v3.w)));
            float2 f;
            f = __half22float2(s0); a0.x += f.x; a0.y += f.y;
            f = __half22float2(s1); a1.x += f.x; a1.y += f.y;
            f = __half22float2(s2); a2.x += f.x; a2.y += f.y;
            f = __half22float2(s3); a3.x += f.x; a3.y += f.y;
        }
    }
    {   // tail: tokens 48, 49
        int k0 = __shfl_sync(0xffffffffu, tB, 16);
        int k1 = __shfl_sync(0xffffffffu, tB, 17);
        if (act) {
            uint4 v0 = __ldg(&T4[(size_t)k0 * 26 + lane]);
            uint4 v1 = __ldg(&T4[(size_t)k1 * 26 + lane]);
            __half2 s0 = __hadd2(asH2(v0.x), asH2(v1.x));
            __half2 s1 = __hadd2(asH2(v0.y), asH2(v1.y));
            __half2 s2 = __hadd2(asH2(v0.z), asH2(v1.z));
            __half2 s3 = __hadd2(asH2(v0.w), asH2(v1.w));
            float2 f;
            f = __half22float2(s0); a0.x += f.x; a0.y += f.y;
            f = __half22float2(s1); a1.x += f.x; a1.y += f.y;
            f = __half22float2(s2); a2.x += f.x; a2.y += f.y;
            f = __half22float2(s3); a3.x += f.x; a3.y += f.y;
        }
    }

    if (act) {
        float f[8] = {a0.x, a0.y, a1.x, a1.y, a2.x, a2.y, a3.x, a3.y};
        int d0 = lane * 8;
        #pragma unroll
        for (int j = 0; j < 8; j++) {
            int d = d0 + j;
            if (d < RAND_DIM) {                     // path_random dim: leaky_relu
                float v = f[j];
                v = (v > 0.f) ? v : 0.01f * v;
                atomicMaxF(&smax[d], v);
            } else {                                // bow dim: stage for the linear
                sbow[w][d - RAND_DIM] = f[j];
            }
        }
    }
    __syncwarp();

    // per-path linear: out[2l,2l+1] = sum_k bow[k] * W[k][2l,2l+1]
    if (act) {
        ull accA = 0ull, accB = 0ull;
        const float* bw = sbow[w];
        #pragma unroll 10
        for (int k = 0; k < VDIM; k += 2) {
            accA = fma2(dup2(bw[k]),     sW2[k * 25 + lane],       accA);
            accB = fma2(dup2(bw[k + 1]), sW2[(k + 1) * 25 + lane], accB);
        }
        float c0, c1, e0, e1;
        unpack2(accA, c0, c1);
        unpack2(accB, e0, e1);
        c0 += e0; c1 += e1;
        int c = 2 * lane;
        float v0 = fmaxf(c0 + __ldg(&b_enc[c]),     0.f);
        float v1 = fmaxf(c1 + __ldg(&b_enc[c + 1]), 0.f);
        atomicMaxF(&smax[RAND_DIM + c],     v0);
        atomicMaxF(&smax[RAND_DIM + c + 1], v1);
    }
    __syncthreads();

    for (int i = tid; i < HDIM; i += 256) atomicMaxF(&g_max[i], smax[i]);

    // ---- fused finalize: last block to finish computes softmax + loss ----
    __threadfence();
    if (tid == 0) s_last = (atomicAdd(&g_done, 1) == NBLK - 1);
    __syncthreads();
    if (!s_last || w != 0) return;

    float part[CLS] = {0.f, 0.f, 0.f, 0.f};
    for (int d = lane; d < HDIM; d += 32) {
        float m = __ldcg(&g_max[d]);
        #pragma unroll
        for (int c = 0; c < CLS; c++)
            part[c] = fmaf(w_out[c * HDIM + d], m, part[c]);
    }
    #pragma unroll
    for (int off = 16; off > 0; off >>= 1) {
        #pragma unroll
        for (int c = 0; c < CLS; c++)
            part[c] += __shfl_down_sync(0xffffffffu, part[c], off);
    }
    if (lane == 0) {
        float logits[CLS], prob[CLS];
        float mx = -CUDART_INF_F;
        #pragma unroll
        for (int c = 0; c < CLS; c++) {
            logits[c] = part[c] + b_out[c];
            mx = fmaxf(mx, logits[c]);
        }
        float s = 0.f;
        #pragma unroll
        for (int c = 0; c < CLS; c++) { prob[c] = expf(logits[c] - mx); s += prob[c]; }
        #pragma unroll
        for (int c = 0; c < CLS; c++) prob[c] /= s;

        int label = 0, best = y[0];
        #pragma unroll
        for (int c = 1; c < CLS; c++) if (y[c] > best) { best = y[c]; label = c; }

        float mx2 = prob[0];
        #pragma unroll
        for (int c = 1; c < CLS; c++) mx2 = fmaxf(mx2, prob[c]);
        float s2 = 0.f;
        #pragma unroll
        for (int c = 0; c < CLS; c++) s2 += expf(prob[c] - mx2);
        float loss = -(prob[label] - (mx2 + logf(s2)));

        for (int c = 0; c < CLS && c < out_size; c++) out[c] = prob[c];
        if (out_size > CLS) out[CLS] = loss;
    }
}

// ---------------------------------------------------------------------------
extern "C" void kernel_launch(void* const* d_in, const int* in_sizes, int n_in,
                              void* d_out, int out_size) {
    const int*   x     = (const int*)  d_in[0];
    const int*   y     = (const int*)  d_in[1];
    const float* E_td  = (const float*)d_in[2];
    const float* E_wae = (const float*)d_in[3];
    const float* W_enc = (const float*)d_in[4];
    const float* b_enc = (const float*)d_in[5];
    const float* w_out = (const float*)d_in[6];
    const float* b_out = (const float*)d_in[7];
    float* out = (float*)d_out;

    convert_kernel<<<1184, 256>>>(E_td, E_wae);
    path_gather_kernel<<<NBLK, 256>>>(x, W_enc, b_enc, w_out, b_out, y,
                                      out, out_size);
}